// round 17
// baseline (speedup 1.0000x reference)
#include <cuda_runtime.h>

#define BATCH 4
#define CCH   32
#define HH    512
#define WW    960
#define HT    128
#define WT    240
#define HW    (HH*WW)      // 491520
#define HTWT  (HT*WT)      // 30720

#define PADL   60                   // covers max disparity ~53
#define SWINP  1056                 // padded whole-row window (mult of 32)
#define NF4    (SWINP/4)            // 264 float4 per channel row
#define QRT4   (NF4/4)              // 66 float4 per quarter-warp task
#define CPASS  4                    // channels per pass
#define NPASS  (CCH/CPASS)          // 8
#define NTHR   512
#define NPIX   480                  // compute threads (2 px each = 960)

__device__ __forceinline__ void cp_async16(void* smem_dst, const void* gsrc, unsigned src_sz)
{
    unsigned dst = (unsigned)__cvta_generic_to_shared(smem_dst);
    asm volatile("cp.async.cg.shared.global [%0], [%1], 16, %2;\n"
                 :: "r"(dst), "l"(gsrc), "r"(src_sz) : "memory");
}
__device__ __forceinline__ void cp_commit()  { asm volatile("cp.async.commit_group;\n" ::: "memory"); }
__device__ __forceinline__ void cp_wait_all(){ asm volatile("cp.async.wait_group 0;\n" ::: "memory"); }

__global__ __launch_bounds__(NTHR, 3)
void tile_warp_kernel(const float* __restrict__ tp,
                      const float* __restrict__ fl,
                      const float* __restrict__ fr,
                      float* __restrict__ out)
{
    __shared__ float s[2][CPASS * SWINP];   // 2*4*1056*4 = 33792 B

    int t    = threadIdx.x;
    int warp = t >> 5;
    int lane = t & 31;
    int y    = blockIdx.x & (HH - 1);
    int b    = blockIdx.x >> 9;             // 512 rows per batch

    // ---- per-pixel-pair setup (t < 480 computes pixels 2t, 2t+1) ----
    int xA = 2 * t;                          // pixels xA, xA+1 share a tile
    float w0 = 0.f, w1 = 0.f;
    float nAm = 0.f, nA0 = 0.f, nAp = 0.f;   // negated masks, pixel A
    float nBm = 0.f, nB0 = 0.f, nBp = 0.f;   // negated masks, pixel B
    int off0 = 1;
    bool d1 = false, d2 = false;
    if (t < NPIX) {
        int ht = y >> 2, wt = xA >> 2;
        int i  = y & 3,  j  = xA & 3;        // j in {0,2}
        int tb = (b * 3 * HT + ht) * WT + wt;
        float d  = __ldg(tp + tb);
        float dx = __ldg(tp + tb + HTWT);
        float dy = __ldg(tp + tb + 2 * HTWT);

        float sxA = (float)xA - d - ((float)j - 1.5f) * dx - ((float)i - 1.5f) * dy;
        float sxB = sxA + 1.f - dx;
        float fA = floorf(sxA), fB = floorf(sxB);
        w0 = sxA - fA;
        w1 = sxB - fB;
        int iA = (int)fA, iB = (int)fB;
        int dlt = min(max(iB - iA, 0), 2);
        d1 = dlt >= 1;
        d2 = dlt >= 2;

        nAm = (sxA >= -1.f && sxA <= (float)(WW - 2)) ? -1.f : 0.f;
        nA0 = (sxA >=  0.f && sxA <= (float)(WW - 1)) ? -1.f : 0.f;
        nAp = (sxA >=  1.f && sxA <= (float)(WW))     ? -1.f : 0.f;
        nBm = (sxB >= -1.f && sxB <= (float)(WW - 2)) ? -1.f : 0.f;
        nB0 = (sxB >=  0.f && sxB <= (float)(WW - 1)) ? -1.f : 0.f;
        nBp = (sxB >=  1.f && sxB <= (float)(WW))     ? -1.f : 0.f;

        off0 = min(max(iA + PADL, 1), SWINP - 6);   // need q[-1..4] in bounds
    }

    const float*  frrow = fr + (size_t)b * CCH * HW + (size_t)y * WW;
    const float2* flp   = (const float2*)(fl + (size_t)b * CCH * HW + (size_t)y * WW) + t;

    // staging role: warp w -> channel (w>>2), quarter-window (w&3)
    int sc    = warp >> 2;                 // 0..3
    int kbase = (warp & 3) * QRT4;         // 0,66,132,198
    const float* ssrc0 = frrow + (size_t)sc * HW - PADL;

    auto stage = [&](int pp, int bb) {
        const float* src = ssrc0 + (size_t)pp * CPASS * HW;
        float* dst = &s[bb][sc * SWINP];
#pragma unroll
        for (int r = 0; r < 3; r++) {
            int k4 = kbase + lane + r * 32;
            if (k4 < kbase + QRT4) {
                int gx = -PADL + 4 * k4;
                unsigned sz = (gx >= 0 && gx < WW) ? 16u : 0u;
                cp_async16(dst + 4 * k4, src + 4 * k4, sz);
            }
        }
        cp_commit();
    };

    float aAm = 0.f, aA0 = 0.f, aAp = 0.f;
    float aBm = 0.f, aB0 = 0.f, aBp = 0.f;

    // ---- prologue ----
    stage(0, 0);
    cp_wait_all();
    __syncthreads();

#pragma unroll
    for (int p = 0; p < NPASS; p++) {
        if (p < NPASS - 1) stage(p + 1, (p + 1) & 1);

        if (t < NPIX) {
            const float* buf = s[p & 1] + off0;
#pragma unroll
            for (int c = 0; c < CPASS; c++) {
                float2 al = __ldcs(flp + (size_t)(p * CPASS + c) * (HW / 2));
                const float* q = buf + c * SWINP;
                float g0 = q[-1], g1 = q[0], g2 = q[1],
                      g3 = q[2],  g4 = q[3], g5 = q[4];

                // pixel A (taps g0..g3, frac w0)
                aAm += fabsf(fmaf(nAm, fmaf(w0, g3 - g2, g2), al.x));
                aA0 += fabsf(fmaf(nA0, fmaf(w0, g2 - g1, g1), al.x));
                aAp += fabsf(fmaf(nAp, fmaf(w0, g1 - g0, g0), al.x));

                // pixel B taps = g[Δ..Δ+3], Δ in {0,1,2}
                float h0 = d1 ? g1 : g0;  h0 = d2 ? g2 : h0;
                float h1 = d1 ? g2 : g1;  h1 = d2 ? g3 : h1;
                float h2 = d1 ? g3 : g2;  h2 = d2 ? g4 : h2;
                float h3 = d1 ? g4 : g3;  h3 = d2 ? g5 : h3;

                aBm += fabsf(fmaf(nBm, fmaf(w1, h3 - h2, h2), al.y));
                aB0 += fabsf(fmaf(nB0, fmaf(w1, h2 - h1, h1), al.y));
                aBp += fabsf(fmaf(nBp, fmaf(w1, h1 - h0, h0), al.y));
            }
        }

        cp_wait_all();
        __syncthreads();
    }

    if (t < NPIX) {
        int ht = y >> 2, wt = xA >> 2;
        int i  = y & 3,  j  = xA & 3;
        int ob = (b * 48 * HT + ht) * WT + wt + (i * 4 + j) * HTWT;
        // pixel A -> channel (i*4+j); pixel B -> channel (i*4+j+1)
        out[ob]                    = aAm;
        out[ob + 16 * HTWT]        = aA0;
        out[ob + 32 * HTWT]        = aAp;
        out[ob + HTWT]             = aBm;
        out[ob + HTWT + 16 * HTWT] = aB0;
        out[ob + HTWT + 32 * HTWT] = aBp;
    }
}

extern "C" void kernel_launch(void* const* d_in, const int* in_sizes, int n_in,
                              void* d_out, int out_size)
{
    const float* tp = nullptr;
    const float* big[2] = {nullptr, nullptr};
    int nbig = 0;
    for (int k = 0; k < n_in; k++) {
        if (in_sizes[k] == BATCH * 3 * HTWT) {
            tp = (const float*)d_in[k];
        } else if (nbig < 2) {
            big[nbig++] = (const float*)d_in[k];
        }
    }
    const float* fl = big[0];
    const float* fr = big[1];
    float* out = (float*)d_out;

    int blocks = BATCH * HH;   // 2048 blocks, one full row each
    tile_warp_kernel<<<blocks, NTHR>>>(tp, fl, fr, out);
}